// round 1
// baseline (speedup 1.0000x reference)
#include <cuda_runtime.h>
#include <stdint.h>

// Problem constants
#define NB    4        // b-values per CTA
#define NT    256      // threads per CTA (NB * 64 channels)
#define DIM   40
#define NPAIR 820      // DIM*(DIM+1)/2 unique symmetric pairs
#define NROWS 860      // pairs + 40 U1 rows
#define TS    16       // table row stride (floats)
#define XROWB 1024     // x_s row stride in bytes (256 threads * 4B)

// Packed coefficient table:
//  rows [0,820): per pair (i<=j): 13 symmetric-folded U2 coeffs (off-diag doubled),
//                pad, then bit-cast byte offsets i*1024, j*1024
//  rows [820,860): per i: 13 U1 coeffs, pad, offset i*1024, 0
__device__ float g_table[NROWS * TS];

__global__ void prep_kernel(const float* __restrict__ U2_0,
                            const float* __restrict__ U1_0,
                            const float* __restrict__ U2_1,
                            const float* __restrict__ U1_1,
                            const float* __restrict__ U2_2,
                            const float* __restrict__ U1_2) {
    int idx = blockIdx.x * blockDim.x + threadIdx.x;
    if (idx >= NROWS) return;
    float row[TS];
#pragma unroll
    for (int k = 0; k < TS; k++) row[k] = 0.0f;

    if (idx < NPAIR) {
        int p = idx;
        int j = 0;
        while ((j + 1) * (j + 2) / 2 <= p) j++;
        int i = p - j * (j + 1) / 2;   // i <= j
        const float* U2b[3] = {U2_0, U2_1, U2_2};
#pragma unroll
        for (int m = 0; m < 13; m++) {
            int l  = (m == 0) ? 0 : ((m < 4) ? 1 : 2);
            int mm = (m == 0) ? 0 : ((m < 4) ? (m - 1) : (m - 4));
            const float* U = U2b[l];
            float v = U[(mm * DIM + i) * DIM + j];
            if (i != j) v += U[(mm * DIM + j) * DIM + i];
            row[m] = v;
        }
        row[13] = 0.0f;
        row[14] = __int_as_float(i * XROWB);
        row[15] = __int_as_float(j * XROWB);
    } else {
        int i = idx - NPAIR;
        const float* U1b[3] = {U1_0, U1_1, U1_2};
#pragma unroll
        for (int m = 0; m < 13; m++) {
            int l  = (m == 0) ? 0 : ((m < 4) ? 1 : 2);
            int mm = (m == 0) ? 0 : ((m < 4) ? (m - 1) : (m - 4));
            row[m] = U1b[l][mm * DIM + i];
        }
        row[13] = 0.0f;
        row[14] = __int_as_float(i * XROWB);
        row[15] = __int_as_float(0);
    }
#pragma unroll
    for (int k = 0; k < TS; k++) g_table[idx * TS + k] = row[k];
}

// ---- packed f32x2 helpers (FFMA2 is only reachable via PTX) ----
__device__ __forceinline__ void fma2(unsigned long long& acc,
                                     unsigned long long u,
                                     unsigned long long y) {
    asm("fma.rn.f32x2 %0, %1, %2, %0;" : "+l"(acc) : "l"(u), "l"(y));
}
__device__ __forceinline__ unsigned long long dup2(float y) {
    unsigned long long r;
    asm("mov.b64 %0, {%1, %1};" : "=l"(r) : "f"(y));
    return r;
}
__device__ __forceinline__ float2 unpk2(unsigned long long v) {
    float2 r;
    asm("mov.b64 {%0, %1}, %2;" : "=f"(r.x), "=f"(r.y) : "l"(v));
    return r;
}

// SMEM layout (floats):
//   [0,      13760)  packed coeff table (55 KB)   } after basis phase, first
//   [13760,  24000)  x_s[40][256]       (40 KB)   } 12288 floats reused for Wlin
//   [24000,  28096)  basis[256][16]     (16 KB)
#define SMEM_FLOATS 28096
#define SMEM_BYTES  (SMEM_FLOATS * 4)

__global__ __launch_bounds__(NT, 2)
void main_kernel(const float* __restrict__ f0,  const float* __restrict__ f1,
                 const float* __restrict__ f2,  const float* __restrict__ f3,
                 const float* __restrict__ attrs,
                 const float* __restrict__ W1_0, const float* __restrict__ W2_0,
                 const float* __restrict__ Wl0,  const float* __restrict__ sc0,
                 const float* __restrict__ W1_1, const float* __restrict__ W2_1,
                 const float* __restrict__ Wl1,  const float* __restrict__ sc1,
                 const float* __restrict__ W1_2, const float* __restrict__ W2_2,
                 const float* __restrict__ Wl2,  const float* __restrict__ sc2,
                 float* __restrict__ out, int B) {
    extern __shared__ float S[];
    float* upkS = S;            // 13760 floats
    float* xS   = S + 13760;    // 10240 floats
    float* basS = S + 24000;    // 4096 floats

    const int tid = threadIdx.x;
    const int bl  = tid >> 6;
    const int c   = tid & 63;
    int b = blockIdx.x * NB + bl;
    const bool active = (b < B);
    if (b >= B) b = B - 1;               // clamp for safe loads
    const int bci = b * 64 + c;

    // cooperative load of packed table (broadcast-friendly, L2-resident)
    {
        const float4* gt4 = (const float4*)g_table;
        float4* up4 = (float4*)upkS;
        for (int k = tid; k < NROWS * TS / 4; k += NT) up4[k] = gt4[k];
    }

    // gather x[40] into smem, transposed [i][tid] for conflict-free LDS
    xS[0 * NT + tid] = f0[bci];
#pragma unroll
    for (int k = 0; k < 3; k++)  xS[(1 + k) * NT + tid]  = f1[bci * 3 + k];
#pragma unroll
    for (int k = 0; k < 9; k++)  xS[(4 + k) * NT + tid]  = f2[bci * 9 + k];
#pragma unroll
    for (int k = 0; k < 27; k++) xS[(13 + k) * NT + tid] = f3[bci * 27 + k];

    // element-aware channel weights: w{1,2}[l] = attrs[b,:] . W{1,2}_l[:,c]
    float w1[3] = {0.f, 0.f, 0.f}, w2[3] = {0.f, 0.f, 0.f};
#pragma unroll
    for (int e = 0; e < 10; e++) {
        float a = __ldg(&attrs[b * 10 + e]);
        w1[0] += a * __ldg(&W1_0[e * 64 + c]);
        w2[0] += a * __ldg(&W2_0[e * 64 + c]);
        w1[1] += a * __ldg(&W1_1[e * 64 + c]);
        w2[1] += a * __ldg(&W2_1[e * 64 + c]);
        w1[2] += a * __ldg(&W1_2[e * 64 + c]);
        w2[2] += a * __ldg(&W2_2[e * 64 + c]);
    }
    __syncthreads();

    // ---- main contraction: a2[m] = sum_pairs u[p][m] * x_i * x_j  (FFMA2) ----
    const char* xb = (const char*)xS + tid * 4;
    unsigned long long a2[7], a1[7];
#pragma unroll
    for (int k = 0; k < 7; k++) { a2[k] = 0ull; a1[k] = 0ull; }

    const ulonglong2* row = (const ulonglong2*)upkS;
#pragma unroll 4
    for (int p = 0; p < NPAIR; p++, row += 4) {
        ulonglong2 q0 = row[0];
        ulonglong2 q1 = row[1];
        ulonglong2 q2 = row[2];
        ulonglong2 q3 = row[3];
        unsigned int io = (unsigned int)(q3.y);
        unsigned int jo = (unsigned int)(q3.y >> 32);
        float xi = *(const float*)(xb + io);
        float xj = *(const float*)(xb + jo);
        unsigned long long yy = dup2(xi * xj);
        fma2(a2[0], q0.x, yy);
        fma2(a2[1], q0.y, yy);
        fma2(a2[2], q1.x, yy);
        fma2(a2[3], q1.y, yy);
        fma2(a2[4], q2.x, yy);
        fma2(a2[5], q2.y, yy);
        fma2(a2[6], q3.x, yy);
    }
    // ---- a1[m] = U1[m,:] . x ----
#pragma unroll 4
    for (int p = 0; p < DIM; p++, row += 4) {
        ulonglong2 q0 = row[0];
        ulonglong2 q1 = row[1];
        ulonglong2 q2 = row[2];
        ulonglong2 q3 = row[3];
        unsigned int io = (unsigned int)(q3.y);
        float xi = *(const float*)(xb + io);
        unsigned long long yy = dup2(xi);
        fma2(a1[0], q0.x, yy);
        fma2(a1[1], q0.y, yy);
        fma2(a1[2], q1.x, yy);
        fma2(a1[3], q1.y, yy);
        fma2(a1[4], q2.x, yy);
        fma2(a1[5], q2.y, yy);
        fma2(a1[6], q3.x, yy);
    }

    // basis[m] = a1[m]*w1[l(m)] + a2[m]*w2[l(m)]
    {
        const int LSEL[14] = {0, 1, 1, 1, 2, 2, 2, 2, 2, 2, 2, 2, 2, 0};
        float* bs = basS + tid * 16;
#pragma unroll
        for (int k = 0; k < 7; k++) {
            float2 v2 = unpk2(a2[k]);
            float2 v1 = unpk2(a1[k]);
            int m0 = 2 * k, m1 = 2 * k + 1;
            bs[m0] = v1.x * w1[LSEL[m0]] + v2.x * w2[LSEL[m0]];
            if (m1 < 13)
                bs[m1] = v1.y * w1[LSEL[m1]] + v2.y * w2[LSEL[m1]];
        }
    }
    __syncthreads();

    // reuse table/x region for Wlin cache: wlS[l*4096 + cc*64 + o]
    float* wlS = S;
    {
        const float4* a0 = (const float4*)Wl0;
        const float4* a1p = (const float4*)Wl1;
        const float4* a2p = (const float4*)Wl2;
        float4* w4 = (float4*)wlS;
        for (int k = tid; k < 1024; k += NT) {
            w4[k]        = a0[k];
            w4[1024 + k] = a1p[k];
            w4[2048 + k] = a2p[k];
        }
    }
    __syncthreads();

    // self-interaction: r[m] = sum_cc basis[b][cc][m] * Wlin_l[cc][c]
    float r[13];
#pragma unroll
    for (int m = 0; m < 13; m++) r[m] = 0.0f;
    const float* bb = basS + bl * 64 * 16;
#pragma unroll 4
    for (int cc = 0; cc < 64; cc++) {
        const float* br = bb + cc * 16;
        float4 b0 = *(const float4*)(br);
        float4 b1 = *(const float4*)(br + 4);
        float4 b2 = *(const float4*)(br + 8);
        float b12 = br[12];
        float wv0 = wlS[cc * 64 + c];
        float wv1 = wlS[4096 + cc * 64 + c];
        float wv2 = wlS[8192 + cc * 64 + c];
        r[0]  += b0.x * wv0;
        r[1]  += b0.y * wv1;
        r[2]  += b0.z * wv1;
        r[3]  += b0.w * wv1;
        r[4]  += b1.x * wv2;
        r[5]  += b1.y * wv2;
        r[6]  += b1.z * wv2;
        r[7]  += b1.w * wv2;
        r[8]  += b2.x * wv2;
        r[9]  += b2.y * wv2;
        r[10] += b2.z * wv2;
        r[11] += b2.w * wv2;
        r[12] += b12  * wv2;
    }

    if (!active) return;

    // outputs: concat [out0 (B,C)] [out1 (B,C,3)] [out2 (B,C,9)]
    float* o0 = out;
    float* o1 = out + (size_t)B * 64;
    float* o2 = out + (size_t)B * 64 * 4;
    const int bo = b * 64 + c;
    o0[bo] = r[0] + sc0[bo];
#pragma unroll
    for (int k = 0; k < 3; k++) o1[bo * 3 + k] = r[1 + k] + __ldg(&sc1[bo * 3 + k]);
#pragma unroll
    for (int k = 0; k < 9; k++) o2[bo * 9 + k] = r[4 + k] + __ldg(&sc2[bo * 9 + k]);
}

extern "C" void kernel_launch(void* const* d_in, const int* in_sizes, int n_in,
                              void* d_out, int out_size) {
    const float* f0    = (const float*)d_in[0];
    const float* f1    = (const float*)d_in[1];
    const float* f2    = (const float*)d_in[2];
    const float* f3    = (const float*)d_in[3];
    const float* attrs = (const float*)d_in[4];
    const float* U2_0  = (const float*)d_in[5];
    const float* U1_0  = (const float*)d_in[6];
    const float* W1_0  = (const float*)d_in[7];
    const float* W2_0  = (const float*)d_in[8];
    const float* Wl0   = (const float*)d_in[9];
    const float* sc0   = (const float*)d_in[10];
    const float* U2_1  = (const float*)d_in[11];
    const float* U1_1  = (const float*)d_in[12];
    const float* W1_1  = (const float*)d_in[13];
    const float* W2_1  = (const float*)d_in[14];
    const float* Wl1   = (const float*)d_in[15];
    const float* sc1   = (const float*)d_in[16];
    const float* U2_2  = (const float*)d_in[17];
    const float* U1_2  = (const float*)d_in[18];
    const float* W1_2  = (const float*)d_in[19];
    const float* W2_2  = (const float*)d_in[20];
    const float* Wl2   = (const float*)d_in[21];
    const float* sc2   = (const float*)d_in[22];

    const int B = in_sizes[0] / 64;

    cudaFuncSetAttribute(main_kernel,
                         cudaFuncAttributeMaxDynamicSharedMemorySize, SMEM_BYTES);

    prep_kernel<<<(NROWS + 255) / 256, 256>>>(U2_0, U1_0, U2_1, U1_1, U2_2, U1_2);

    const int grid = (B + NB - 1) / NB;
    main_kernel<<<grid, NT, SMEM_BYTES>>>(f0, f1, f2, f3, attrs,
                                          W1_0, W2_0, Wl0, sc0,
                                          W1_1, W2_1, Wl1, sc1,
                                          W1_2, W2_2, Wl2, sc2,
                                          (float*)d_out, B);
}